// round 12
// baseline (speedup 1.0000x reference)
#include <cuda_runtime.h>
#include <cuda_fp16.h>
#include <math_constants.h>
#include <cstdint>

#define B_ 8
#define C_ 256
#define N_ 2048
#define SCALE 0.0625f  // 1/sqrt(256)

// ------------------------- device scratch ----------------------------------
__device__ __align__(16) __half g_q16[(size_t)B_ * C_ * N_];
__device__ __align__(16) __half g_k16[(size_t)B_ * C_ * N_];
__device__ __align__(16) __half g_v16[(size_t)B_ * C_ * N_];
__device__ __align__(16) __half g_w16[(size_t)B_ * N_ * N_];  // unnormalized exp (E)
__device__ __align__(16) float  g_partl[(size_t)B_ * 16 * N_]; // per-i-tile col sums
__device__ __align__(16) float  g_invl[(size_t)B_ * N_];       // 1/L per column

// ------------------------------ PTX helpers --------------------------------
__device__ __forceinline__ uint32_t smem_u32(const void* p) {
    uint32_t a;
    asm("{ .reg .u64 t; cvta.to.shared.u64 t, %1; cvt.u32.u64 %0, t; }"
        : "=r"(a) : "l"(p));
    return a;
}
__device__ __forceinline__ void cp16(uint32_t dst, const void* src) {
    asm volatile("cp.async.cg.shared.global [%0], [%1], 16;" :: "r"(dst), "l"(src));
}
#define CP_COMMIT() asm volatile("cp.async.commit_group;" ::: "memory")
#define CP_WAIT1()  asm volatile("cp.async.wait_group 1;" ::: "memory")
#define CP_WAIT0()  asm volatile("cp.async.wait_group 0;" ::: "memory")

#define LDSM4(r0, r1, r2, r3, a)                                               \
    asm volatile("ldmatrix.sync.aligned.m8n8.x4.shared.b16 {%0,%1,%2,%3},[%4];"\
                 : "=r"(r0), "=r"(r1), "=r"(r2), "=r"(r3) : "r"(a))
#define LDSM4T(r0, r1, r2, r3, a)                                              \
    asm volatile("ldmatrix.sync.aligned.m8n8.x4.trans.shared.b16 "             \
                 "{%0,%1,%2,%3},[%4];"                                         \
                 : "=r"(r0), "=r"(r1), "=r"(r2), "=r"(r3) : "r"(a))

__device__ __forceinline__ void mma_f16(float4& d, const uint32_t a[4],
                                        uint32_t b0, uint32_t b1) {
    asm volatile(
        "mma.sync.aligned.m16n8k16.row.col.f32.f16.f16.f32 "
        "{%0,%1,%2,%3}, {%4,%5,%6,%7}, {%8,%9}, {%0,%1,%2,%3};"
        : "+f"(d.x), "+f"(d.y), "+f"(d.z), "+f"(d.w)
        : "r"(a[0]), "r"(a[1]), "r"(a[2]), "r"(a[3]), "r"(b0), "r"(b1));
}

// ============================================================================
// fp32 -> fp16 convert, all three tensors in one launch.
// ============================================================================
__global__ __launch_bounds__(256)
void cvt16_all(const float* __restrict__ q, const float* __restrict__ k,
               const float* __restrict__ v)
{
    const float* s = (blockIdx.y == 0) ? q : (blockIdx.y == 1) ? k : v;
    __half* d = (blockIdx.y == 0) ? g_q16 : (blockIdx.y == 1) ? g_k16 : g_v16;
    size_t i = ((size_t)blockIdx.x * 256 + threadIdx.x) * 4;
    float4 x = *(const float4*)(s + i);
    *(__half2*)(d + i)     = __floats2half2_rn(x.x, x.y);
    *(__half2*)(d + i + 2) = __floats2half2_rn(x.z, x.w);
}

// ============================================================================
// fp16 GEMM (cp.async + ldmatrix + mma.m16n8k16), BK=32, 3-stage pipeline.
//   MODE 1: E[b,i,j] = exp(SCALE * sum_c K(c,i) Q(c,j))  -> g_w16 (fp16)
//           + per-CTA column sums -> g_partl[b][i_tile][j]
//   MODE 2: out[b,c,j] = invl[b][j] * sum_i V(c,i) * E16(i,j)
//           + streams W[b,i,j] = E16(i,j) * invl[b][j] from its smem tiles
// CTA 128x128, 256 thr = 8 warps (2x4), warp 64x32.
// Stage: A 8KB + B 8KB = 16KB; 3 stages = 48KB static smem.
// ============================================================================
template <int MODE>
__global__ __launch_bounds__(256, 2)
void gemm_f16(float* __restrict__ Dg, float* __restrict__ Wg)
{
    __shared__ __align__(256) uint8_t smem[3 * 16384];
    const uint32_t sb = smem_u32(smem);

    const __half* Ag = (MODE == 1) ? g_k16 : g_v16;
    const __half* Bg = (MODE == 1) ? g_q16 : g_w16;
    const size_t batchA = (size_t)C_ * N_;
    const size_t batchB = (MODE == 1) ? (size_t)C_ * N_ : (size_t)N_ * N_;
    const int Ktot = (MODE == 1) ? C_ : N_;
    const int S = Ktot >> 5;

    const int tid  = threadIdx.x;
    const int w    = tid >> 5;
    const int lane = tid & 31;
    const int qr   = lane >> 2;
    const int qc   = lane & 3;
    const int g2   = lane >> 3;
    const int tr   = lane & 7;
    const int wm   = (w >> 2) * 64;
    const int wn   = (w & 3) * 32;
    const int m0   = blockIdx.y * 128;
    const int j0   = blockIdx.x * 128;

    const __half* A  = Ag + (size_t)blockIdx.z * batchA;
    const __half* Bp = Bg + (size_t)blockIdx.z * batchB;

    float4 acc[4][4];
#pragma unroll
    for (int mt = 0; mt < 4; mt++)
#pragma unroll
        for (int nt = 0; nt < 4; nt++)
            acc[mt][nt] = make_float4(0.f, 0.f, 0.f, 0.f);

    // ---- cp.async per-thread fixed mapping ----
    const int brow0 = tid >> 4, bch = tid & 15;   // B (and MODE1 A): 2 rounds

    auto issue = [&](int s, int buf) {
        const uint32_t bb = sb + (uint32_t)buf * 16384;
        const int k0 = s << 5;
        if (MODE == 1) {
#pragma unroll
            for (int r = 0; r < 2; r++) {
                const int row = brow0 + r * 16;
                cp16(bb + (uint32_t)row * 256 + (uint32_t)((bch ^ (row & 7)) << 4),
                     A + (size_t)(k0 + row) * N_ + m0 + bch * 8);
            }
        } else {
#pragma unroll
            for (int r = 0; r < 2; r++) {
                const int idx = tid + r * 256;
                const int row = idx >> 2, ch = idx & 3;
                cp16(bb + (uint32_t)row * 64 + (uint32_t)((ch ^ ((row >> 1) & 3)) << 4),
                     A + (size_t)(m0 + row) * N_ + k0 + ch * 8);
            }
        }
#pragma unroll
        for (int r = 0; r < 2; r++) {
            const int row = brow0 + r * 16;
            cp16(bb + 8192u + (uint32_t)row * 256 + (uint32_t)((bch ^ (row & 7)) << 4),
                 Bp + (size_t)(k0 + row) * N_ + j0 + bch * 8);
        }
        CP_COMMIT();
    };

    issue(0, 0);
    issue(1, 1);

    // ---- MODE 2: invl preload + W-write setup ----
    float ivw[8];
    float* Wrow = nullptr;
    if (MODE == 2) {
        const float* ivp = g_invl + (size_t)blockIdx.z * N_ + j0 + bch * 8;
#pragma unroll
        for (int e = 0; e < 8; e++) ivw[e] = ivp[e];
        Wrow = Wg + (size_t)blockIdx.z * ((size_t)N_ * N_) + j0 + bch * 8;
    }

    // ---- ldmatrix address precompute (kk=0 base; kk=1 = +4096 / ^32) ----
    uint32_t aoff[4], boff[2];
    if (MODE == 1) {
        const int kr = tr + ((g2 >> 1) << 3);
#pragma unroll
        for (int mt = 0; mt < 4; mt++) {
            const int ch = ((wm + mt * 16) >> 3) + (g2 & 1);
            aoff[mt] = (uint32_t)kr * 256 + (uint32_t)((ch ^ (kr & 7)) << 4);
        }
    } else {
#pragma unroll
        for (int mt = 0; mt < 4; mt++) {
            const int mr = wm + mt * 16 + tr + ((g2 & 1) << 3);
            const int ch = (g2 >> 1) ^ ((mr >> 1) & 3);
            aoff[mt] = (uint32_t)mr * 64 + (uint32_t)(ch << 4);
        }
    }
    {
        const int kr = tr + ((g2 & 1) << 3);
#pragma unroll
        for (int p = 0; p < 2; p++) {
            const int ch = ((wn + p * 16) >> 3) + (g2 >> 1);
            boff[p] = 8192u + (uint32_t)kr * 256 + (uint32_t)((ch ^ (kr & 7)) << 4);
        }
    }

    int cbuf = 0, ibuf = 2;
#pragma unroll 1
    for (int s = 0; s < S; s++) {
        if (s == S - 1) { CP_WAIT0(); } else { CP_WAIT1(); }
        __syncthreads();
        if (s + 2 < S) issue(s + 2, ibuf);

        const uint32_t bb = sb + (uint32_t)cbuf * 16384;

#pragma unroll
        for (int kk = 0; kk < 2; kk++) {
            uint32_t bf[2][4];
#pragma unroll
            for (int p = 0; p < 2; p++)
                LDSM4T(bf[p][0], bf[p][1], bf[p][2], bf[p][3],
                       bb + boff[p] + (uint32_t)kk * 4096);

#pragma unroll
            for (int mt = 0; mt < 4; mt++) {
                uint32_t af[4];
                if (MODE == 1) {
                    LDSM4T(af[0], af[1], af[2], af[3], bb + aoff[mt] + (uint32_t)kk * 4096);
                } else {
                    LDSM4(af[0], af[1], af[2], af[3], (bb + aoff[mt]) ^ ((uint32_t)kk << 5));
                }
#pragma unroll
                for (int p = 0; p < 2; p++) {
                    mma_f16(acc[mt][p * 2],     af, bf[p][0], bf[p][1]);
                    mma_f16(acc[mt][p * 2 + 1], af, bf[p][2], bf[p][3]);
                }
            }
        }

        // ---- MODE 2: stream W = E16 * invl from this stage's B tile ----
        if (MODE == 2) {
            if ((int)blockIdx.y == (s >= (S >> 1))) {
#pragma unroll
                for (int r = 0; r < 2; r++) {
                    const int row = brow0 + r * 16;
                    uint4 raw = *(const uint4*)(smem + cbuf * 16384 + 8192 +
                                                row * 256 + ((bch ^ (row & 7)) << 4));
                    const __half2* h = (const __half2*)&raw;
                    float2 f0 = __half22float2(h[0]);
                    float2 f1 = __half22float2(h[1]);
                    float2 f2 = __half22float2(h[2]);
                    float2 f3 = __half22float2(h[3]);
                    float* wp = Wrow + (size_t)(s * 32 + row) * N_;
                    *(float4*)wp       = make_float4(f0.x * ivw[0], f0.y * ivw[1],
                                                     f1.x * ivw[2], f1.y * ivw[3]);
                    *(float4*)(wp + 4) = make_float4(f2.x * ivw[4], f2.y * ivw[5],
                                                     f3.x * ivw[6], f3.y * ivw[7]);
                }
            }
        }

        cbuf = (cbuf == 2) ? 0 : cbuf + 1;
        ibuf = (ibuf == 2) ? 0 : ibuf + 1;
    }

    // ---------------- epilogue ----------------
    if (MODE == 2) {
        float* Dp = Dg + (size_t)blockIdx.z * ((size_t)C_ * N_);
        const float* ivp = g_invl + (size_t)blockIdx.z * N_;
#pragma unroll
        for (int mt = 0; mt < 4; mt++) {
            const int r0 = m0 + wm + mt * 16 + qr;
#pragma unroll
            for (int nt = 0; nt < 4; nt++) {
                const int c0 = j0 + wn + nt * 8 + qc * 2;
                const float2 iv = *(const float2*)&ivp[c0];
                *(float2*)&Dp[(size_t)r0 * N_ + c0] =
                    make_float2(acc[mt][nt].x * iv.x, acc[mt][nt].y * iv.y);
                *(float2*)&Dp[(size_t)(r0 + 8) * N_ + c0] =
                    make_float2(acc[mt][nt].z * iv.x, acc[mt][nt].w * iv.y);
            }
        }
    } else {
        // exp(scale*logit) -> fp16 E; column sums -> partials.
        // red aliases pipeline buffer 2 (stage S-1 uses buffer (S-1)%3 = 1
        // for S=8, so no warp still reads buffer 2 past the last sync).
        float (*red)[128] = (float (*)[128])(smem + 2 * 16384);
        __half* Hp = g_w16 + (size_t)blockIdx.z * ((size_t)N_ * N_);
        float cs[4][2];
#pragma unroll
        for (int nt = 0; nt < 4; nt++) { cs[nt][0] = 0.f; cs[nt][1] = 0.f; }
#pragma unroll
        for (int mt = 0; mt < 4; mt++) {
            const int r0 = m0 + wm + mt * 16 + qr;
#pragma unroll
            for (int nt = 0; nt < 4; nt++) {
                const int c0 = j0 + wn + nt * 8 + qc * 2;
                float e0 = __expf(acc[mt][nt].x * SCALE);
                float e1 = __expf(acc[mt][nt].y * SCALE);
                float e2 = __expf(acc[mt][nt].z * SCALE);
                float e3 = __expf(acc[mt][nt].w * SCALE);
                *(__half2*)&Hp[(size_t)r0 * N_ + c0]       = __floats2half2_rn(e0, e1);
                *(__half2*)&Hp[(size_t)(r0 + 8) * N_ + c0] = __floats2half2_rn(e2, e3);
                cs[nt][0] += e0 + e2;
                cs[nt][1] += e1 + e3;
            }
        }
#pragma unroll
        for (int nt = 0; nt < 4; nt++)
#pragma unroll
            for (int e = 0; e < 2; e++) {
                float v = cs[nt][e];
#pragma unroll
                for (int o = 16; o >= 4; o >>= 1)
                    v += __shfl_down_sync(0xffffffffu, v, o);
                cs[nt][e] = v;
            }
        if (qr == 0) {
#pragma unroll
            for (int nt = 0; nt < 4; nt++)
#pragma unroll
                for (int e = 0; e < 2; e++)
                    red[w >> 2][wn + nt * 8 + qc * 2 + e] = cs[nt][e];
        }
        __syncthreads();
        if (tid < 128) {
            g_partl[((size_t)blockIdx.z * 16 + blockIdx.y) * N_ + j0 + tid] =
                red[0][tid] + red[1][tid];
        }
    }
}

// ============================================================================
// reduce: L[b][j] = sum over 16 i-tiles; store 1/L.
// ============================================================================
__global__ __launch_bounds__(256)
void reduce_l()
{
    const int t = blockIdx.x * 256 + threadIdx.x;    // over B_*N_
    const int b = t >> 11, j = t & (N_ - 1);
    float s = 0.f;
#pragma unroll
    for (int it = 0; it < 16; it++)
        s += g_partl[((size_t)b * 16 + it) * N_ + j];
    g_invl[t] = 1.f / s;
}

// ============================================================================
extern "C" void kernel_launch(void* const* d_in, const int* in_sizes, int n_in,
                              void* d_out, int out_size)
{
    const float* q = (const float*)d_in[0];
    const float* k = (const float*)d_in[1];
    const float* v = (const float*)d_in[2];

    float* out = (float*)d_out;                        // [B, C, N]
    float* w   = (float*)d_out + (size_t)B_ * C_ * N_; // [B, N, N]

    dim3 gc((unsigned)(((size_t)B_ * C_ * N_) / 1024), 3);
    cvt16_all<<<gc, 256>>>(q, k, v);

    // GEMM1 + exp -> fp16 E + partial column sums
    dim3 g1(N_ / 128, N_ / 128, B_);   // (16,16,8)
    gemm_f16<1><<<g1, 256>>>(nullptr, nullptr);

    reduce_l<<<(B_ * N_) / 256, 256>>>();

    // GEMM2: out = (V @ E16) * invl, and streams W = E16 * invl
    dim3 g2(N_ / 128, C_ / 128, B_);   // (16,2,8)
    gemm_f16<2><<<g2, 256>>>(out, w);
}

// round 13
// speedup vs baseline: 1.0460x; 1.0460x over previous
#include <cuda_runtime.h>
#include <cuda_fp16.h>
#include <math_constants.h>
#include <cstdint>

#define B_ 8
#define C_ 256
#define N_ 2048
#define SCALE 0.0625f  // 1/sqrt(256)

// ------------------------- device scratch ----------------------------------
__device__ __align__(16) __half g_q16[(size_t)B_ * C_ * N_];
__device__ __align__(16) __half g_k16[(size_t)B_ * C_ * N_];
__device__ __align__(16) __half g_v16[(size_t)B_ * C_ * N_];
__device__ __align__(16) __half g_w16[(size_t)B_ * N_ * N_];  // unnormalized exp (E)
__device__ __align__(16) float  g_partl[(size_t)B_ * 16 * N_]; // per-i-tile col sums
__device__ __align__(16) float  g_invl[(size_t)B_ * N_];       // 1/L per column

// ------------------------------ PTX helpers --------------------------------
__device__ __forceinline__ uint32_t smem_u32(const void* p) {
    uint32_t a;
    asm("{ .reg .u64 t; cvta.to.shared.u64 t, %1; cvt.u32.u64 %0, t; }"
        : "=r"(a) : "l"(p));
    return a;
}
__device__ __forceinline__ void cp16(uint32_t dst, const void* src) {
    asm volatile("cp.async.cg.shared.global [%0], [%1], 16;" :: "r"(dst), "l"(src));
}
#define CP_COMMIT() asm volatile("cp.async.commit_group;" ::: "memory")
#define CP_WAIT1()  asm volatile("cp.async.wait_group 1;" ::: "memory")
#define CP_WAIT0()  asm volatile("cp.async.wait_group 0;" ::: "memory")

#define LDSM4(r0, r1, r2, r3, a)                                               \
    asm volatile("ldmatrix.sync.aligned.m8n8.x4.shared.b16 {%0,%1,%2,%3},[%4];"\
                 : "=r"(r0), "=r"(r1), "=r"(r2), "=r"(r3) : "r"(a))
#define LDSM4T(r0, r1, r2, r3, a)                                              \
    asm volatile("ldmatrix.sync.aligned.m8n8.x4.trans.shared.b16 "             \
                 "{%0,%1,%2,%3},[%4];"                                         \
                 : "=r"(r0), "=r"(r1), "=r"(r2), "=r"(r3) : "r"(a))

__device__ __forceinline__ void mma_f16(float4& d, const uint32_t a[4],
                                        uint32_t b0, uint32_t b1) {
    asm volatile(
        "mma.sync.aligned.m16n8k16.row.col.f32.f16.f16.f32 "
        "{%0,%1,%2,%3}, {%4,%5,%6,%7}, {%8,%9}, {%0,%1,%2,%3};"
        : "+f"(d.x), "+f"(d.y), "+f"(d.z), "+f"(d.w)
        : "r"(a[0]), "r"(a[1]), "r"(a[2]), "r"(a[3]), "r"(b0), "r"(b1));
}

// ============================================================================
// fp32 -> fp16 convert, all three tensors in one launch.
// ============================================================================
__global__ __launch_bounds__(256)
void cvt16_all(const float* __restrict__ q, const float* __restrict__ k,
               const float* __restrict__ v)
{
    const float* s = (blockIdx.y == 0) ? q : (blockIdx.y == 1) ? k : v;
    __half* d = (blockIdx.y == 0) ? g_q16 : (blockIdx.y == 1) ? g_k16 : g_v16;
    size_t i = ((size_t)blockIdx.x * 256 + threadIdx.x) * 4;
    float4 x = *(const float4*)(s + i);
    *(__half2*)(d + i)     = __floats2half2_rn(x.x, x.y);
    *(__half2*)(d + i + 2) = __floats2half2_rn(x.z, x.w);
}

// ============================================================================
// GEMM1: E[b,i,j] = exp(SCALE * sum_c K(c,i) Q(c,j)) -> g_w16 (fp16)
//        + per-CTA column sums -> g_partl[b][i_tile][j]
// CTA 128x128, 256 thr = 8 warps (2x4), warp 64x32, BK=32, 3-stage cp.async.
// ============================================================================
__global__ __launch_bounds__(256, 2)
void gemm1_f16()
{
    __shared__ __align__(256) uint8_t smem[3 * 16384];
    const uint32_t sb = smem_u32(smem);

    const int S = C_ >> 5;   // 8

    const int tid  = threadIdx.x;
    const int w    = tid >> 5;
    const int lane = tid & 31;
    const int qr   = lane >> 2;
    const int qc   = lane & 3;
    const int g2   = lane >> 3;
    const int tr   = lane & 7;
    const int wm   = (w >> 2) * 64;
    const int wn   = (w & 3) * 32;
    const int m0   = blockIdx.y * 128;
    const int j0   = blockIdx.x * 128;

    const __half* A  = g_k16 + (size_t)blockIdx.z * ((size_t)C_ * N_);
    const __half* Bp = g_q16 + (size_t)blockIdx.z * ((size_t)C_ * N_);

    float4 acc[4][4];
#pragma unroll
    for (int mt = 0; mt < 4; mt++)
#pragma unroll
        for (int nt = 0; nt < 4; nt++)
            acc[mt][nt] = make_float4(0.f, 0.f, 0.f, 0.f);

    const int brow0 = tid >> 4, bch = tid & 15;

    auto issue = [&](int s, int buf) {
        const uint32_t bb = sb + (uint32_t)buf * 16384;
        const int k0 = s << 5;
#pragma unroll
        for (int r = 0; r < 2; r++) {
            const int row = brow0 + r * 16;
            cp16(bb + (uint32_t)row * 256 + (uint32_t)((bch ^ (row & 7)) << 4),
                 A + (size_t)(k0 + row) * N_ + m0 + bch * 8);
            cp16(bb + 8192u + (uint32_t)row * 256 + (uint32_t)((bch ^ (row & 7)) << 4),
                 Bp + (size_t)(k0 + row) * N_ + j0 + bch * 8);
        }
        CP_COMMIT();
    };

    issue(0, 0);
    issue(1, 1);

    uint32_t aoff[4], boff[2];
    {
        const int kr = tr + ((g2 >> 1) << 3);
#pragma unroll
        for (int mt = 0; mt < 4; mt++) {
            const int ch = ((wm + mt * 16) >> 3) + (g2 & 1);
            aoff[mt] = (uint32_t)kr * 256 + (uint32_t)((ch ^ (kr & 7)) << 4);
        }
        const int krb = tr + ((g2 & 1) << 3);
#pragma unroll
        for (int p = 0; p < 2; p++) {
            const int ch = ((wn + p * 16) >> 3) + (g2 >> 1);
            boff[p] = 8192u + (uint32_t)krb * 256 + (uint32_t)((ch ^ (krb & 7)) << 4);
        }
    }

    int cbuf = 0, ibuf = 2;
#pragma unroll 1
    for (int s = 0; s < S; s++) {
        if (s == S - 1) { CP_WAIT0(); } else { CP_WAIT1(); }
        __syncthreads();
        if (s + 2 < S) issue(s + 2, ibuf);

        const uint32_t bb = sb + (uint32_t)cbuf * 16384;
#pragma unroll
        for (int kk = 0; kk < 2; kk++) {
            uint32_t bf[2][4];
#pragma unroll
            for (int p = 0; p < 2; p++)
                LDSM4T(bf[p][0], bf[p][1], bf[p][2], bf[p][3],
                       bb + boff[p] + (uint32_t)kk * 4096);
#pragma unroll
            for (int mt = 0; mt < 4; mt++) {
                uint32_t af[4];
                LDSM4T(af[0], af[1], af[2], af[3], bb + aoff[mt] + (uint32_t)kk * 4096);
#pragma unroll
                for (int p = 0; p < 2; p++) {
                    mma_f16(acc[mt][p * 2],     af, bf[p][0], bf[p][1]);
                    mma_f16(acc[mt][p * 2 + 1], af, bf[p][2], bf[p][3]);
                }
            }
        }
        cbuf = (cbuf == 2) ? 0 : cbuf + 1;
        ibuf = (ibuf == 2) ? 0 : ibuf + 1;
    }

    // epilogue: exp -> fp16 E; column sums -> partials (red aliases buffer 2;
    // last stage S-1=7 consumed buffer 1, so buffer 2 is free after last sync)
    float (*red)[128] = (float (*)[128])(smem + 2 * 16384);
    __half* Hp = g_w16 + (size_t)blockIdx.z * ((size_t)N_ * N_);
    float cs[4][2];
#pragma unroll
    for (int nt = 0; nt < 4; nt++) { cs[nt][0] = 0.f; cs[nt][1] = 0.f; }
#pragma unroll
    for (int mt = 0; mt < 4; mt++) {
        const int r0 = m0 + wm + mt * 16 + qr;
#pragma unroll
        for (int nt = 0; nt < 4; nt++) {
            const int c0 = j0 + wn + nt * 8 + qc * 2;
            float e0 = __expf(acc[mt][nt].x * SCALE);
            float e1 = __expf(acc[mt][nt].y * SCALE);
            float e2 = __expf(acc[mt][nt].z * SCALE);
            float e3 = __expf(acc[mt][nt].w * SCALE);
            *(__half2*)&Hp[(size_t)r0 * N_ + c0]       = __floats2half2_rn(e0, e1);
            *(__half2*)&Hp[(size_t)(r0 + 8) * N_ + c0] = __floats2half2_rn(e2, e3);
            cs[nt][0] += e0 + e2;
            cs[nt][1] += e1 + e3;
        }
    }
#pragma unroll
    for (int nt = 0; nt < 4; nt++)
#pragma unroll
        for (int e = 0; e < 2; e++) {
            float v = cs[nt][e];
#pragma unroll
            for (int o = 16; o >= 4; o >>= 1)
                v += __shfl_down_sync(0xffffffffu, v, o);
            cs[nt][e] = v;
        }
    if (qr == 0) {
#pragma unroll
        for (int nt = 0; nt < 4; nt++)
#pragma unroll
            for (int e = 0; e < 2; e++)
                red[w >> 2][wn + nt * 8 + qc * 2 + e] = cs[nt][e];
    }
    __syncthreads();
    if (tid < 128) {
        g_partl[((size_t)blockIdx.z * 16 + blockIdx.y) * N_ + j0 + tid] =
            red[0][tid] + red[1][tid];
    }
}

// ============================================================================
// reduce: L[b][j] = sum over 16 i-tiles; store 1/L.
// ============================================================================
__global__ __launch_bounds__(256)
void reduce_l()
{
    const int t = blockIdx.x * 256 + threadIdx.x;    // over B_*N_
    const int b = t >> 11, j = t & (N_ - 1);
    float s = 0.f;
#pragma unroll
    for (int it = 0; it < 16; it++)
        s += g_partl[((size_t)b * 16 + it) * N_ + j];
    g_invl[t] = 1.f / s;
}

// ============================================================================
// GEMM2: out[b,c,j] = invl[b][j] * sum_i V(c,i) * E16(i,j)
//        + streams W[b,i,j] = E16(i,j) * invl[b][j] from its smem tiles.
// ONE CTA per j-strip: tile 256(c) x 128(j), 512 thr = 16 warps (4x4),
// warp 64x32, BK=32, 3-stage (stage = A 16KB + B 8KB = 24KB; 72KB dynamic).
// grid (16, 8): blockIdx.x = j-strip, blockIdx.y = batch.
// ============================================================================
#define G2_STAGE 24576
#define G2_SMEM  (3 * G2_STAGE)

__global__ __launch_bounds__(512, 1)
void gemm2_f16(float* __restrict__ Dg, float* __restrict__ Wg)
{
    extern __shared__ __align__(256) uint8_t smem[];
    const uint32_t sb = smem_u32(smem);

    const int S = N_ >> 5;   // 64

    const int tid  = threadIdx.x;
    const int w    = tid >> 5;
    const int lane = tid & 31;
    const int qr   = lane >> 2;
    const int qc   = lane & 3;
    const int g2   = lane >> 3;
    const int tr   = lane & 7;
    const int wm   = (w >> 2) * 64;   // 4 warp-rows over 256 c
    const int wn   = (w & 3) * 32;    // 4 warp-cols over 128 j
    const int j0   = blockIdx.x * 128;
    const int b    = blockIdx.y;

    const __half* A  = g_v16 + (size_t)b * ((size_t)C_ * N_);
    const __half* Bp = g_w16 + (size_t)b * ((size_t)N_ * N_);

    float4 acc[4][4];
#pragma unroll
    for (int mt = 0; mt < 4; mt++)
#pragma unroll
        for (int nt = 0; nt < 4; nt++)
            acc[mt][nt] = make_float4(0.f, 0.f, 0.f, 0.f);

    // ---- cp.async mapping ----
    const int brow = tid >> 4, bch = tid & 15;       // B: 32 rows x 16 chunks
    const uint32_t bswz = (uint32_t)brow * 256 + (uint32_t)((bch ^ (brow & 7)) << 4);

    auto issue = [&](int s, int buf) {
        const uint32_t bb = sb + (uint32_t)buf * G2_STAGE;
        const int k0 = s << 5;
#pragma unroll
        for (int r = 0; r < 2; r++) {                // A: 256 rows x 4 chunks
            const int idx = tid + r * 512;
            const int row = idx >> 2, ch = idx & 3;
            cp16(bb + (uint32_t)row * 64 + (uint32_t)((ch ^ ((row >> 1) & 3)) << 4),
                 A + (size_t)row * N_ + k0 + ch * 8);
        }
        cp16(bb + 16384u + bswz, Bp + (size_t)(k0 + brow) * N_ + j0 + bch * 8);
        CP_COMMIT();
    };

    issue(0, 0);
    issue(1, 1);

    // ---- invl preload + W-write setup ----
    float ivw[8];
    {
        const float* ivp = g_invl + (size_t)b * N_ + j0 + bch * 8;
#pragma unroll
        for (int e = 0; e < 8; e++) ivw[e] = ivp[e];
    }
    float* Wrow = Wg + (size_t)b * ((size_t)N_ * N_) + j0 + bch * 8;

    // ---- ldmatrix address precompute ----
    uint32_t aoff[4], boff[2];
#pragma unroll
    for (int mt = 0; mt < 4; mt++) {
        const int mr = wm + mt * 16 + tr + ((g2 & 1) << 3);
        const int ch = (g2 >> 1) ^ ((mr >> 1) & 3);
        aoff[mt] = (uint32_t)mr * 64 + (uint32_t)(ch << 4);
    }
    {
        const int kr = tr + ((g2 & 1) << 3);
#pragma unroll
        for (int p = 0; p < 2; p++) {
            const int ch = ((wn + p * 16) >> 3) + (g2 >> 1);
            boff[p] = 16384u + (uint32_t)kr * 256 + (uint32_t)((ch ^ (kr & 7)) << 4);
        }
    }

    int cbuf = 0, ibuf = 2;
#pragma unroll 1
    for (int s = 0; s < S; s++) {
        if (s == S - 1) { CP_WAIT0(); } else { CP_WAIT1(); }
        __syncthreads();
        if (s + 2 < S) issue(s + 2, ibuf);

        const uint32_t bb = sb + (uint32_t)cbuf * G2_STAGE;
#pragma unroll
        for (int kk = 0; kk < 2; kk++) {
            uint32_t bf[2][4];
#pragma unroll
            for (int p = 0; p < 2; p++)
                LDSM4T(bf[p][0], bf[p][1], bf[p][2], bf[p][3],
                       bb + boff[p] + (uint32_t)kk * 4096);
#pragma unroll
            for (int mt = 0; mt < 4; mt++) {
                uint32_t af[4];
                LDSM4(af[0], af[1], af[2], af[3], (bb + aoff[mt]) ^ ((uint32_t)kk << 5));
#pragma unroll
                for (int p = 0; p < 2; p++) {
                    mma_f16(acc[mt][p * 2],     af, bf[p][0], bf[p][1]);
                    mma_f16(acc[mt][p * 2 + 1], af, bf[p][2], bf[p][3]);
                }
            }
        }

        // ---- stream W = E16 * invl from this stage's B tile (1 chunk/thread)
        {
            uint4 raw = *(const uint4*)(smem + (uint32_t)cbuf * G2_STAGE + 16384u + bswz);
            const __half2* h = (const __half2*)&raw;
            float2 f0 = __half22float2(h[0]);
            float2 f1 = __half22float2(h[1]);
            float2 f2 = __half22float2(h[2]);
            float2 f3 = __half22float2(h[3]);
            float* wp = Wrow + (size_t)(s * 32 + brow) * N_;
            *(float4*)wp       = make_float4(f0.x * ivw[0], f0.y * ivw[1],
                                             f1.x * ivw[2], f1.y * ivw[3]);
            *(float4*)(wp + 4) = make_float4(f2.x * ivw[4], f2.y * ivw[5],
                                             f3.x * ivw[6], f3.y * ivw[7]);
        }

        cbuf = (cbuf == 2) ? 0 : cbuf + 1;
        ibuf = (ibuf == 2) ? 0 : ibuf + 1;
    }

    // ---- epilogue ----
    float* Dp = Dg + (size_t)b * ((size_t)C_ * N_);
    const float* ivp = g_invl + (size_t)b * N_;
#pragma unroll
    for (int mt = 0; mt < 4; mt++) {
        const int r0 = wm + mt * 16 + qr;
#pragma unroll
        for (int nt = 0; nt < 4; nt++) {
            const int c0 = j0 + wn + nt * 8 + qc * 2;
            const float2 iv = *(const float2*)&ivp[c0];
            *(float2*)&Dp[(size_t)r0 * N_ + c0] =
                make_float2(acc[mt][nt].x * iv.x, acc[mt][nt].y * iv.y);
            *(float2*)&Dp[(size_t)(r0 + 8) * N_ + c0] =
                make_float2(acc[mt][nt].z * iv.x, acc[mt][nt].w * iv.y);
        }
    }
}

// ============================================================================
extern "C" void kernel_launch(void* const* d_in, const int* in_sizes, int n_in,
                              void* d_out, int out_size)
{
    const float* q = (const float*)d_in[0];
    const float* k = (const float*)d_in[1];
    const float* v = (const float*)d_in[2];

    float* out = (float*)d_out;                        // [B, C, N]
    float* w   = (float*)d_out + (size_t)B_ * C_ * N_; // [B, N, N]

    cudaFuncSetAttribute(gemm2_f16, cudaFuncAttributeMaxDynamicSharedMemorySize,
                         G2_SMEM);

    dim3 gc((unsigned)(((size_t)B_ * C_ * N_) / 1024), 3);
    cvt16_all<<<gc, 256>>>(q, k, v);

    // GEMM1 + exp -> fp16 E + partial column sums
    dim3 g1(N_ / 128, N_ / 128, B_);   // (16,16,8)
    gemm1_f16<<<g1, 256>>>();

    reduce_l<<<(B_ * N_) / 256, 256>>>();

    // GEMM2: out = (V @ E16) * invl, streams W = E16 * invl
    dim3 g2(N_ / 128, B_);             // (16,8)
    gemm2_f16<<<g2, 512, G2_SMEM>>>(out, w);
}

// round 14
// speedup vs baseline: 1.0483x; 1.0022x over previous
#include <cuda_runtime.h>
#include <cuda_fp16.h>
#include <math_constants.h>
#include <cstdint>

#define B_ 8
#define C_ 256
#define N_ 2048
#define SCALE 0.0625f  // 1/sqrt(256)

// ------------------------- device scratch ----------------------------------
__device__ __align__(16) __half g_q16[(size_t)B_ * C_ * N_];
__device__ __align__(16) __half g_k16[(size_t)B_ * C_ * N_];
__device__ __align__(16) __half g_v16[(size_t)B_ * C_ * N_];
__device__ __align__(16) __half g_w16[(size_t)B_ * N_ * N_];  // unnormalized exp (E)
__device__ __align__(16) float  g_partl[(size_t)B_ * 16 * N_]; // per-i-tile col sums
__device__ __align__(16) float  g_invl[(size_t)B_ * N_];       // 1/L per column

// ------------------------------ PTX helpers --------------------------------
__device__ __forceinline__ uint32_t smem_u32(const void* p) {
    uint32_t a;
    asm("{ .reg .u64 t; cvta.to.shared.u64 t, %1; cvt.u32.u64 %0, t; }"
        : "=r"(a) : "l"(p));
    return a;
}
__device__ __forceinline__ void cp16(uint32_t dst, const void* src) {
    asm volatile("cp.async.cg.shared.global [%0], [%1], 16;" :: "r"(dst), "l"(src));
}
#define CP_COMMIT() asm volatile("cp.async.commit_group;" ::: "memory")
#define CP_WAIT2()  asm volatile("cp.async.wait_group 2;" ::: "memory")
#define CP_WAIT1()  asm volatile("cp.async.wait_group 1;" ::: "memory")
#define CP_WAIT0()  asm volatile("cp.async.wait_group 0;" ::: "memory")

#define LDSM4(r0, r1, r2, r3, a)                                               \
    asm volatile("ldmatrix.sync.aligned.m8n8.x4.shared.b16 {%0,%1,%2,%3},[%4];"\
                 : "=r"(r0), "=r"(r1), "=r"(r2), "=r"(r3) : "r"(a))
#define LDSM4T(r0, r1, r2, r3, a)                                              \
    asm volatile("ldmatrix.sync.aligned.m8n8.x4.trans.shared.b16 "             \
                 "{%0,%1,%2,%3},[%4];"                                         \
                 : "=r"(r0), "=r"(r1), "=r"(r2), "=r"(r3) : "r"(a))

__device__ __forceinline__ void mma_f16(float4& d, const uint32_t a[4],
                                        uint32_t b0, uint32_t b1) {
    asm volatile(
        "mma.sync.aligned.m16n8k16.row.col.f32.f16.f16.f32 "
        "{%0,%1,%2,%3}, {%4,%5,%6,%7}, {%8,%9}, {%0,%1,%2,%3};"
        : "+f"(d.x), "+f"(d.y), "+f"(d.z), "+f"(d.w)
        : "r"(a[0]), "r"(a[1]), "r"(a[2]), "r"(a[3]), "r"(b0), "r"(b1));
}

// pipeline wait helper: stage s must be complete; issues go up to s+3.
__device__ __forceinline__ void pipe_wait(int s, int S) {
    if (s < S - 2)      { CP_WAIT2(); }
    else if (s == S - 2){ CP_WAIT1(); }
    else                { CP_WAIT0(); }
}

// ============================================================================
// fp32 -> fp16 convert, all three tensors in one launch.
// ============================================================================
__global__ __launch_bounds__(256)
void cvt16_all(const float* __restrict__ q, const float* __restrict__ k,
               const float* __restrict__ v)
{
    const float* s = (blockIdx.y == 0) ? q : (blockIdx.y == 1) ? k : v;
    __half* d = (blockIdx.y == 0) ? g_q16 : (blockIdx.y == 1) ? g_k16 : g_v16;
    size_t i = ((size_t)blockIdx.x * 256 + threadIdx.x) * 4;
    float4 x = *(const float4*)(s + i);
    *(__half2*)(d + i)     = __floats2half2_rn(x.x, x.y);
    *(__half2*)(d + i + 2) = __floats2half2_rn(x.z, x.w);
}

// ============================================================================
// GEMM1: E[b,i,j] = exp(SCALE * sum_c K(c,i) Q(c,j)) -> g_w16 (fp16)
//        + per-CTA column sums -> g_partl[b][i_tile][j]
// CTA 128x128, 256 thr = 8 warps (2x4), warp 64x32, BK=32.
// 4-stage cp.async (3 in flight), 16KB/stage, 64KB dynamic smem, 2 CTAs/SM.
// ============================================================================
#define G1_STAGE 16384
#define G1_SMEM  (4 * G1_STAGE)

__global__ __launch_bounds__(256, 2)
void gemm1_f16()
{
    extern __shared__ __align__(256) uint8_t smem[];
    const uint32_t sb = smem_u32(smem);

    const int S = C_ >> 5;   // 8

    const int tid  = threadIdx.x;
    const int w    = tid >> 5;
    const int lane = tid & 31;
    const int qr   = lane >> 2;
    const int qc   = lane & 3;
    const int g2   = lane >> 3;
    const int tr   = lane & 7;
    const int wm   = (w >> 2) * 64;
    const int wn   = (w & 3) * 32;
    const int m0   = blockIdx.y * 128;
    const int j0   = blockIdx.x * 128;

    const __half* A  = g_k16 + (size_t)blockIdx.z * ((size_t)C_ * N_);
    const __half* Bp = g_q16 + (size_t)blockIdx.z * ((size_t)C_ * N_);

    float4 acc[4][4];
#pragma unroll
    for (int mt = 0; mt < 4; mt++)
#pragma unroll
        for (int nt = 0; nt < 4; nt++)
            acc[mt][nt] = make_float4(0.f, 0.f, 0.f, 0.f);

    const int brow0 = tid >> 4, bch = tid & 15;

    auto issue = [&](int s) {
        const uint32_t bb = sb + (uint32_t)(s & 3) * G1_STAGE;
        const int k0 = s << 5;
#pragma unroll
        for (int r = 0; r < 2; r++) {
            const int row = brow0 + r * 16;
            cp16(bb + (uint32_t)row * 256 + (uint32_t)((bch ^ (row & 7)) << 4),
                 A + (size_t)(k0 + row) * N_ + m0 + bch * 8);
            cp16(bb + 8192u + (uint32_t)row * 256 + (uint32_t)((bch ^ (row & 7)) << 4),
                 Bp + (size_t)(k0 + row) * N_ + j0 + bch * 8);
        }
        CP_COMMIT();
    };

    issue(0); issue(1); issue(2);

    uint32_t aoff[4], boff[2];
    {
        const int kr = tr + ((g2 >> 1) << 3);
#pragma unroll
        for (int mt = 0; mt < 4; mt++) {
            const int ch = ((wm + mt * 16) >> 3) + (g2 & 1);
            aoff[mt] = (uint32_t)kr * 256 + (uint32_t)((ch ^ (kr & 7)) << 4);
        }
        const int krb = tr + ((g2 & 1) << 3);
#pragma unroll
        for (int p = 0; p < 2; p++) {
            const int ch = ((wn + p * 16) >> 3) + (g2 >> 1);
            boff[p] = 8192u + (uint32_t)krb * 256 + (uint32_t)((ch ^ (krb & 7)) << 4);
        }
    }

#pragma unroll 1
    for (int s = 0; s < S; s++) {
        pipe_wait(s, S);
        __syncthreads();
        if (s + 3 < S) issue(s + 3);

        const uint32_t bb = sb + (uint32_t)(s & 3) * G1_STAGE;
#pragma unroll
        for (int kk = 0; kk < 2; kk++) {
            uint32_t bf[2][4];
#pragma unroll
            for (int p = 0; p < 2; p++)
                LDSM4T(bf[p][0], bf[p][1], bf[p][2], bf[p][3],
                       bb + boff[p] + (uint32_t)kk * 4096);
#pragma unroll
            for (int mt = 0; mt < 4; mt++) {
                uint32_t af[4];
                LDSM4T(af[0], af[1], af[2], af[3], bb + aoff[mt] + (uint32_t)kk * 4096);
#pragma unroll
                for (int p = 0; p < 2; p++) {
                    mma_f16(acc[mt][p * 2],     af, bf[p][0], bf[p][1]);
                    mma_f16(acc[mt][p * 2 + 1], af, bf[p][2], bf[p][3]);
                }
            }
        }
    }

    // epilogue: exp -> fp16 E; column sums -> partials.
    // red aliases stage buffer 0 (last touched at s=4; all warps are past
    // s>=5 top barriers, so no reader remains).
    float (*red)[128] = (float (*)[128])smem;
    __half* Hp = g_w16 + (size_t)blockIdx.z * ((size_t)N_ * N_);
    float cs[4][2];
#pragma unroll
    for (int nt = 0; nt < 4; nt++) { cs[nt][0] = 0.f; cs[nt][1] = 0.f; }
#pragma unroll
    for (int mt = 0; mt < 4; mt++) {
        const int r0 = m0 + wm + mt * 16 + qr;
#pragma unroll
        for (int nt = 0; nt < 4; nt++) {
            const int c0 = j0 + wn + nt * 8 + qc * 2;
            float e0 = __expf(acc[mt][nt].x * SCALE);
            float e1 = __expf(acc[mt][nt].y * SCALE);
            float e2 = __expf(acc[mt][nt].z * SCALE);
            float e3 = __expf(acc[mt][nt].w * SCALE);
            *(__half2*)&Hp[(size_t)r0 * N_ + c0]       = __floats2half2_rn(e0, e1);
            *(__half2*)&Hp[(size_t)(r0 + 8) * N_ + c0] = __floats2half2_rn(e2, e3);
            cs[nt][0] += e0 + e2;
            cs[nt][1] += e1 + e3;
        }
    }
#pragma unroll
    for (int nt = 0; nt < 4; nt++)
#pragma unroll
        for (int e = 0; e < 2; e++) {
            float v = cs[nt][e];
#pragma unroll
            for (int o = 16; o >= 4; o >>= 1)
                v += __shfl_down_sync(0xffffffffu, v, o);
            cs[nt][e] = v;
        }
    __syncthreads();   // all warps done with stage buffers before aliasing
    if (qr == 0) {
#pragma unroll
        for (int nt = 0; nt < 4; nt++)
#pragma unroll
            for (int e = 0; e < 2; e++)
                red[w >> 2][wn + nt * 8 + qc * 2 + e] = cs[nt][e];
    }
    __syncthreads();
    if (tid < 128) {
        g_partl[((size_t)blockIdx.z * 16 + blockIdx.y) * N_ + j0 + tid] =
            red[0][tid] + red[1][tid];
    }
}

// ============================================================================
// reduce: L[b][j] = sum over 16 i-tiles; store 1/L.
// ============================================================================
__global__ __launch_bounds__(256)
void reduce_l()
{
    const int t = blockIdx.x * 256 + threadIdx.x;    // over B_*N_
    const int b = t >> 11, j = t & (N_ - 1);
    float s = 0.f;
#pragma unroll
    for (int it = 0; it < 16; it++)
        s += g_partl[((size_t)b * 16 + it) * N_ + j];
    g_invl[t] = 1.f / s;
}

// ============================================================================
// GEMM2: out[b,c,j] = invl[b][j] * sum_i V(c,i) * E16(i,j)
//        + streams W[b,i,j] = E16(i,j) * invl[b][j] from its smem tiles.
// ONE CTA per j-strip: tile 256(c) x 128(j), 512 thr = 16 warps (4x4),
// warp 64x32, BK=32. 4-stage cp.async (3 in flight), 24KB/stage, 96KB smem.
// grid (16, 8): blockIdx.x = j-strip, blockIdx.y = batch.
// ============================================================================
#define G2_STAGE 24576
#define G2_SMEM  (4 * G2_STAGE)

__global__ __launch_bounds__(512, 1)
void gemm2_f16(float* __restrict__ Dg, float* __restrict__ Wg)
{
    extern __shared__ __align__(256) uint8_t smem[];
    const uint32_t sb = smem_u32(smem);

    const int S = N_ >> 5;   // 64

    const int tid  = threadIdx.x;
    const int w    = tid >> 5;
    const int lane = tid & 31;
    const int qr   = lane >> 2;
    const int qc   = lane & 3;
    const int g2   = lane >> 3;
    const int tr   = lane & 7;
    const int wm   = (w >> 2) * 64;   // 4 warp-rows over 256 c
    const int wn   = (w & 3) * 32;    // 4 warp-cols over 128 j
    const int j0   = blockIdx.x * 128;
    const int b    = blockIdx.y;

    const __half* A  = g_v16 + (size_t)b * ((size_t)C_ * N_);
    const __half* Bp = g_w16 + (size_t)b * ((size_t)N_ * N_);

    float4 acc[4][4];
#pragma unroll
    for (int mt = 0; mt < 4; mt++)
#pragma unroll
        for (int nt = 0; nt < 4; nt++)
            acc[mt][nt] = make_float4(0.f, 0.f, 0.f, 0.f);

    const int brow = tid >> 4, bch = tid & 15;       // B: 32 rows x 16 chunks
    const uint32_t bswz = (uint32_t)brow * 256 + (uint32_t)((bch ^ (brow & 7)) << 4);

    auto issue = [&](int s) {
        const uint32_t bb = sb + (uint32_t)(s & 3) * G2_STAGE;
        const int k0 = s << 5;
#pragma unroll
        for (int r = 0; r < 2; r++) {                // A: 256 rows x 4 chunks
            const int idx = tid + r * 512;
            const int row = idx >> 2, ch = idx & 3;
            cp16(bb + (uint32_t)row * 64 + (uint32_t)((ch ^ ((row >> 1) & 3)) << 4),
                 A + (size_t)row * N_ + k0 + ch * 8);
        }
        cp16(bb + 16384u + bswz, Bp + (size_t)(k0 + brow) * N_ + j0 + bch * 8);
        CP_COMMIT();
    };

    issue(0); issue(1); issue(2);

    float ivw[8];
    {
        const float* ivp = g_invl + (size_t)b * N_ + j0 + bch * 8;
#pragma unroll
        for (int e = 0; e < 8; e++) ivw[e] = ivp[e];
    }
    float* Wrow = Wg + (size_t)b * ((size_t)N_ * N_) + j0 + bch * 8;

    uint32_t aoff[4], boff[2];
#pragma unroll
    for (int mt = 0; mt < 4; mt++) {
        const int mr = wm + mt * 16 + tr + ((g2 & 1) << 3);
        const int ch = (g2 >> 1) ^ ((mr >> 1) & 3);
        aoff[mt] = (uint32_t)mr * 64 + (uint32_t)(ch << 4);
    }
    {
        const int kr = tr + ((g2 & 1) << 3);
#pragma unroll
        for (int p = 0; p < 2; p++) {
            const int ch = ((wn + p * 16) >> 3) + (g2 >> 1);
            boff[p] = 16384u + (uint32_t)kr * 256 + (uint32_t)((ch ^ (kr & 7)) << 4);
        }
    }

#pragma unroll 1
    for (int s = 0; s < S; s++) {
        pipe_wait(s, S);
        __syncthreads();
        if (s + 3 < S) issue(s + 3);

        const uint32_t bb = sb + (uint32_t)(s & 3) * G2_STAGE;
#pragma unroll
        for (int kk = 0; kk < 2; kk++) {
            uint32_t bf[2][4];
#pragma unroll
            for (int p = 0; p < 2; p++)
                LDSM4T(bf[p][0], bf[p][1], bf[p][2], bf[p][3],
                       bb + boff[p] + (uint32_t)kk * 4096);
#pragma unroll
            for (int mt = 0; mt < 4; mt++) {
                uint32_t af[4];
                LDSM4(af[0], af[1], af[2], af[3], (bb + aoff[mt]) ^ ((uint32_t)kk << 5));
#pragma unroll
                for (int p = 0; p < 2; p++) {
                    mma_f16(acc[mt][p * 2],     af, bf[p][0], bf[p][1]);
                    mma_f16(acc[mt][p * 2 + 1], af, bf[p][2], bf[p][3]);
                }
            }
        }

        // ---- stream W = E16 * invl from this stage's B tile (1 chunk/thread)
        {
            uint4 raw = *(const uint4*)(smem + (uint32_t)(s & 3) * G2_STAGE + 16384u + bswz);
            const __half2* h = (const __half2*)&raw;
            float2 f0 = __half22float2(h[0]);
            float2 f1 = __half22float2(h[1]);
            float2 f2 = __half22float2(h[2]);
            float2 f3 = __half22float2(h[3]);
            float* wp = Wrow + (size_t)(s * 32 + brow) * N_;
            *(float4*)wp       = make_float4(f0.x * ivw[0], f0.y * ivw[1],
                                             f1.x * ivw[2], f1.y * ivw[3]);
            *(float4*)(wp + 4) = make_float4(f2.x * ivw[4], f2.y * ivw[5],
                                             f3.x * ivw[6], f3.y * ivw[7]);
        }
    }

    // ---- epilogue ----
    float* Dp = Dg + (size_t)b * ((size_t)C_ * N_);
    const float* ivp = g_invl + (size_t)b * N_;
#pragma unroll
    for (int mt = 0; mt < 4; mt++) {
        const int r0 = wm + mt * 16 + qr;
#pragma unroll
        for (int nt = 0; nt < 4; nt++) {
            const int c0 = j0 + wn + nt * 8 + qc * 2;
            const float2 iv = *(const float2*)&ivp[c0];
            *(float2*)&Dp[(size_t)r0 * N_ + c0] =
                make_float2(acc[mt][nt].x * iv.x, acc[mt][nt].y * iv.y);
            *(float2*)&Dp[(size_t)(r0 + 8) * N_ + c0] =
                make_float2(acc[mt][nt].z * iv.x, acc[mt][nt].w * iv.y);
        }
    }
}

// ============================================================================
extern "C" void kernel_launch(void* const* d_in, const int* in_sizes, int n_in,
                              void* d_out, int out_size)
{
    const float* q = (const float*)d_in[0];
    const float* k = (const float*)d_in[1];
    const float* v = (const float*)d_in[2];

    float* out = (float*)d_out;                        // [B, C, N]
    float* w   = (float*)d_out + (size_t)B_ * C_ * N_; // [B, N, N]

    cudaFuncSetAttribute(gemm1_f16, cudaFuncAttributeMaxDynamicSharedMemorySize,
                         G1_SMEM);
    cudaFuncSetAttribute(gemm2_f16, cudaFuncAttributeMaxDynamicSharedMemorySize,
                         G2_SMEM);

    dim3 gc((unsigned)(((size_t)B_ * C_ * N_) / 1024), 3);
    cvt16_all<<<gc, 256>>>(q, k, v);

    // GEMM1 + exp -> fp16 E + partial column sums
    dim3 g1(N_ / 128, N_ / 128, B_);   // (16,16,8)
    gemm1_f16<<<g1, 256, G1_SMEM>>>();

    reduce_l<<<(B_ * N_) / 256, 256>>>();

    // GEMM2: out = (V @ E16) * invl, streams W = E16 * invl
    dim3 g2(N_ / 128, B_);             // (16,8)
    gemm2_f16<<<g2, 512, G2_SMEM>>>(out, w);
}